// round 3
// baseline (speedup 1.0000x reference)
#include <cuda_runtime.h>
#include <cstdint>
#include <cstddef>

// ---------------- problem constants ----------------
#define SEQ   2048
#define BATCH 16
#define DIN   512
#define HID   512
#define MROWS (SEQ*BATCH)      // 32768 rows (s*16+b)
#define NDIR  (3*HID)          // 1536 gate cols per direction
#define NCOLS (2*NDIR)         // 3072 (fw | bw)

// ---------------- GEMM tiling ----------------
#define BM 256
#define BN 128
#define BK 32
#define KTILES (DIN/BK)        // 16
#define NTHREADS 256
#define STAGE_FLOATS ((BM+BN)*BK)          // 12288 floats = 48KB
#define SMEM_BYTES (2*STAGE_FLOATS*4)      // 96KB

// gate scratch: [MROWS][NCOLS] fp32 raw pre-activations (~402 MB)
__device__ float g_gates[(size_t)MROWS * NCOLS];

// ---------------- helpers ----------------
static __device__ __forceinline__ uint32_t smem_u32(const void* p) {
    uint32_t a;
    asm("{ .reg .u64 t; cvta.to.shared.u64 t, %1; cvt.u32.u64 %0, t; }"
        : "=r"(a) : "l"(p));
    return a;
}
static __device__ __forceinline__ void cp_async16(uint32_t saddr, const void* gaddr) {
    asm volatile("cp.async.ca.shared.global [%0], [%1], 16;"
                 :: "r"(saddr), "l"(gaddr) : "memory");
}
static __device__ __forceinline__ void cp_commit() {
    asm volatile("cp.async.commit_group;" ::: "memory");
}
template <int N>
static __device__ __forceinline__ void cp_wait() {
    asm volatile("cp.async.wait_group %0;" :: "n"(N) : "memory");
}
static __device__ __forceinline__ uint32_t f2tf32(float v) {
    uint32_t r;
    asm("cvt.rna.tf32.f32 %0, %1;" : "=r"(r) : "f"(v));
    return r;
}
static __device__ __forceinline__ void mma_tf32(float* d, const uint32_t* a, const uint32_t* b) {
    asm volatile(
        "mma.sync.aligned.m16n8k8.row.col.f32.tf32.tf32.f32 "
        "{%0,%1,%2,%3}, {%4,%5,%6,%7}, {%8,%9}, {%0,%1,%2,%3};"
        : "+f"(d[0]), "+f"(d[1]), "+f"(d[2]), "+f"(d[3])
        : "r"(a[0]), "r"(a[1]), "r"(a[2]), "r"(a[3]), "r"(b[0]), "r"(b[1]));
}

// smem element address (float index) within a [rows][32] tile with 16B XOR swizzle
static __device__ __forceinline__ int swz_idx(int row, int col) {
    return row * 32 + (((col >> 2) ^ (row & 7)) << 2) + (col & 3);
}

// ---------------- GEMM kernel ----------------
// grid: (24 n-tiles, 128 m-tiles), 256 threads, 1 CTA/SM (96KB smem)
__global__ void __launch_bounds__(NTHREADS, 1)
gemm_kernel(const float* __restrict__ X,
            const float* __restrict__ Wfw,
            const float* __restrict__ Wbw)
{
    extern __shared__ float smem[];
    const int tid  = threadIdx.x;
    const int lane = tid & 31;
    const int wid  = tid >> 5;
    const int gid  = lane >> 2;          // 0..7
    const int tig  = lane & 3;           // 0..3
    const int warp_m = (wid >> 1) * 64;  // 0,64,128,192
    const int warp_n = (wid & 1) * 64;   // 0,64

    const int ntile = blockIdx.x;        // 0..23
    const int m0    = blockIdx.y * BM;
    const float* Wdir   = (ntile < 12) ? Wfw : Wbw;
    const int   n_local = ((ntile < 12) ? ntile : (ntile - 12)) * BN;
    const int   ncol0   = ntile * BN;

    const float* Ag = X    + (size_t)m0      * DIN;
    const float* Bg = Wdir + (size_t)n_local * DIN;

    float* sA0 = smem;
    float* sB0 = smem + BM * BK;

    // stage loader: A 2048 float4 (8/thread), B 1024 float4 (4/thread)
    auto load_stage = [&](int kt, int stage) {
        float* sA = sA0 + stage * STAGE_FLOATS;
        float* sB = sB0 + stage * STAGE_FLOATS;
        const int k0 = kt * BK;
        #pragma unroll
        for (int i = 0; i < 8; i++) {
            int idx = tid + i * NTHREADS;
            int row = idx >> 3, c4 = idx & 7;
            int sw = c4 ^ (row & 7);
            cp_async16(smem_u32(sA + row * 32 + sw * 4),
                       Ag + (size_t)row * DIN + k0 + c4 * 4);
        }
        #pragma unroll
        for (int i = 0; i < 4; i++) {
            int idx = tid + i * NTHREADS;
            int row = idx >> 3, c4 = idx & 7;
            int sw = c4 ^ (row & 7);
            cp_async16(smem_u32(sB + row * 32 + sw * 4),
                       Bg + (size_t)row * DIN + k0 + c4 * 4);
        }
        cp_commit();
    };

    float acc[4][8][4];
    #pragma unroll
    for (int mi = 0; mi < 4; mi++)
        #pragma unroll
        for (int ni = 0; ni < 8; ni++)
            #pragma unroll
            for (int k = 0; k < 4; k++) acc[mi][ni][k] = 0.0f;

    load_stage(0, 0);

    for (int kt = 0; kt < KTILES; kt++) {
        if (kt + 1 < KTILES) {
            load_stage(kt + 1, (kt + 1) & 1);
            cp_wait<1>();
        } else {
            cp_wait<0>();
        }
        __syncthreads();

        const float* sA = sA0 + (kt & 1) * STAGE_FLOATS;
        const float* sB = sB0 + (kt & 1) * STAGE_FLOATS;

        #pragma unroll
        for (int ks = 0; ks < 4; ks++) {
            const int kcol = ks * 8 + tig;
            uint32_t a[4][4];
            #pragma unroll
            for (int mi = 0; mi < 4; mi++) {
                int r0 = warp_m + mi * 16 + gid;
                int r1 = r0 + 8;
                a[mi][0] = f2tf32(sA[swz_idx(r0, kcol)]);
                a[mi][1] = f2tf32(sA[swz_idx(r1, kcol)]);
                a[mi][2] = f2tf32(sA[swz_idx(r0, kcol + 4)]);
                a[mi][3] = f2tf32(sA[swz_idx(r1, kcol + 4)]);
            }
            uint32_t b[8][2];
            #pragma unroll
            for (int ni = 0; ni < 8; ni++) {
                int n = warp_n + ni * 8 + gid;
                b[ni][0] = f2tf32(sB[swz_idx(n, kcol)]);
                b[ni][1] = f2tf32(sB[swz_idx(n, kcol + 4)]);
            }
            #pragma unroll
            for (int mi = 0; mi < 4; mi++)
                #pragma unroll
                for (int ni = 0; ni < 8; ni++)
                    mma_tf32(acc[mi][ni], a[mi], b[ni]);
        }
        __syncthreads();
    }

    // epilogue: float2 stores of (c0,c1) and (c2,c3)
    #pragma unroll
    for (int mi = 0; mi < 4; mi++) {
        int r = m0 + warp_m + mi * 16 + gid;
        #pragma unroll
        for (int ni = 0; ni < 8; ni++) {
            int c = ncol0 + warp_n + ni * 8 + tig * 2;
            float2 v01 = make_float2(acc[mi][ni][0], acc[mi][ni][1]);
            float2 v23 = make_float2(acc[mi][ni][2], acc[mi][ni][3]);
            *(float2*)(g_gates + (size_t)r * NCOLS + c)       = v01;
            *(float2*)(g_gates + (size_t)(r + 8) * NCOLS + c) = v23;
        }
    }
}

// ---------------- activation + fo-pool scan ----------------
static __device__ __forceinline__ float fast_exp2(float x) {
    float y; asm("ex2.approx.f32 %0, %1;" : "=f"(y) : "f"(x)); return y;
}
static __device__ __forceinline__ float fast_rcp(float x) {
    float y; asm("rcp.approx.f32 %0, %1;" : "=f"(y) : "f"(x)); return y;
}
static __device__ __forceinline__ float fast_sig(float x) {
    return fast_rcp(1.0f + fast_exp2(-1.4426950408889634f * x));
}
static __device__ __forceinline__ float fast_tanh(float x) {
    return fmaf(2.0f, fast_sig(2.0f * x), -1.0f);
}

// one thread per (dir, b, h) channel; fw ascends s, bw descends s (no flips).
__global__ void __launch_bounds__(128)
scan_kernel(const float* __restrict__ bfw,
            const float* __restrict__ bbw,
            float* __restrict__ out)
{
    const int ch  = blockIdx.x * 128 + threadIdx.x;   // 0..16383
    const int dir = ch >> 13;
    const int c   = ch & 8191;
    const int b   = c >> 9;
    const int h   = c & 511;

    const float* bias = dir ? bbw : bfw;
    const float bz = bias[h];
    const float bf = bias[HID + h];
    const float bo = bias[2 * HID + h];

    const float* g  = g_gates + (size_t)b * NCOLS + dir * NDIR + h;
    float*       ob = out + (size_t)b * (2 * HID) + dir * HID + h;

    const size_t gstride = (size_t)BATCH * NCOLS;
    const size_t ostride = (size_t)BATCH * 2 * HID;

    float hst = 0.0f;
    if (dir == 0) {
        #pragma unroll 8
        for (int s = 0; s < SEQ; s++) {
            size_t go = (size_t)s * gstride;
            float z = fast_tanh(g[go] + bz);
            float f = fast_sig(g[go + HID] + bf);
            float o = fast_sig(g[go + 2 * HID] + bo);
            hst = fmaf(1.0f - f, hst, f * z);
            ob[(size_t)s * ostride] = o * hst;
        }
    } else {
        #pragma unroll 8
        for (int s = SEQ - 1; s >= 0; s--) {
            size_t go = (size_t)s * gstride;
            float z = fast_tanh(g[go] + bz);
            float f = fast_sig(g[go + HID] + bf);
            float o = fast_sig(g[go + 2 * HID] + bo);
            hst = fmaf(1.0f - f, hst, f * z);
            ob[(size_t)s * ostride] = o * hst;
        }
    }
}

// ---------------- launch ----------------
extern "C" void kernel_launch(void* const* d_in, const int* in_sizes, int n_in,
                              void* d_out, int out_size)
{
    (void)in_sizes; (void)n_in; (void)out_size;
    const float* X   = (const float*)d_in[0];
    const float* Wfw = (const float*)d_in[1];
    const float* bfw = (const float*)d_in[2];
    const float* Wbw = (const float*)d_in[3];
    const float* bbw = (const float*)d_in[4];
    float* out = (float*)d_out;

    cudaFuncSetAttribute(gemm_kernel,
                         cudaFuncAttributeMaxDynamicSharedMemorySize, SMEM_BYTES);
    gemm_kernel<<<dim3(24, 128), NTHREADS, SMEM_BYTES>>>(X, Wfw, Wbw);
    scan_kernel<<<128, 128>>>(bfw, bbw, out);
}

// round 7
// speedup vs baseline: 1.5053x; 1.5053x over previous
#include <cuda_runtime.h>
#include <cuda_fp16.h>
#include <cstdint>
#include <cstddef>

// ---------------- problem constants ----------------
#define SEQ   2048
#define BATCH 16
#define DIN   512
#define HID   512
#define MROWS (SEQ*BATCH)      // 32768 rows (s*16+b)
#define NDIR  (3*HID)          // 1536 gate cols per direction
#define NCOLS (2*NDIR)         // 3072 (fw | bw)
#define XCNT  ((size_t)MROWS*DIN)
#define WCNT  ((size_t)NDIR*DIN)

// ---------------- GEMM tiling (fp16 mma m16n8k16) ----------------
#define BM 256
#define BN 128
#define BK 64                  // halves per k-tile (128B rows)
#define KTILES (DIN/BK)        // 8
#define NTHREADS 256
#define STAGE_HALFS ((BM+BN)*BK)              // 24576 halves = 48KB
#define SMEM_BYTES (2*STAGE_HALFS*2)          // 96KB

// ---------------- scan chunking ----------------
#define NCH    16384           // dir*8192 + b*512 + h
#define CHUNK  128
#define NCHUNK (SEQ/CHUNK)     // 16
#define GSTRIDE (BATCH*NCOLS)  // 49152 floats per s
#define OSTRIDE (BATCH*2*HID)  // 16384 floats per s

// ---------------- device scratch ----------------
__device__ float  g_gates[(size_t)MROWS * NCOLS];   // raw pre-activations (~402MB)
__device__ __half g_Xh[XCNT];                       // fp16 X
__device__ __half g_Wh[2*WCNT];                     // fp16 [Wfw;Wbw]
__device__ float2 g_AC[NCH * NCHUNK];               // per-chunk (A, C)
__device__ float  g_hinit[NCH * NCHUNK];            // h at chunk start

// ---------------- helpers ----------------
static __device__ __forceinline__ uint32_t smem_u32(const void* p) {
    uint32_t a;
    asm("{ .reg .u64 t; cvta.to.shared.u64 t, %1; cvt.u32.u64 %0, t; }"
        : "=r"(a) : "l"(p));
    return a;
}
static __device__ __forceinline__ void cp_async16(uint32_t saddr, const void* gaddr) {
    asm volatile("cp.async.ca.shared.global [%0], [%1], 16;"
                 :: "r"(saddr), "l"(gaddr) : "memory");
}
static __device__ __forceinline__ void cp_commit() {
    asm volatile("cp.async.commit_group;" ::: "memory");
}
template <int N>
static __device__ __forceinline__ void cp_wait() {
    asm volatile("cp.async.wait_group %0;" :: "n"(N) : "memory");
}
static __device__ __forceinline__ void ldsm_x4(uint32_t* r, uint32_t addr) {
    asm volatile("ldmatrix.sync.aligned.m8n8.x4.shared.b16 {%0,%1,%2,%3}, [%4];"
                 : "=r"(r[0]), "=r"(r[1]), "=r"(r[2]), "=r"(r[3]) : "r"(addr));
}
static __device__ __forceinline__ void mma_f16(float* d, const uint32_t* a,
                                               uint32_t b0, uint32_t b1) {
    asm volatile(
        "mma.sync.aligned.m16n8k16.row.col.f32.f16.f16.f32 "
        "{%0,%1,%2,%3}, {%4,%5,%6,%7}, {%8,%9}, {%0,%1,%2,%3};"
        : "+f"(d[0]), "+f"(d[1]), "+f"(d[2]), "+f"(d[3])
        : "r"(a[0]), "r"(a[1]), "r"(a[2]), "r"(a[3]), "r"(b0), "r"(b1));
}

// ---------------- fp32 -> fp16 pre-convert ----------------
// one vec4 per thread; total (XCNT + 2*WCNT)/4 = 4587520 vec4 -> 17920 blocks
__global__ void __launch_bounds__(256)
convert_kernel(const float* __restrict__ X,
               const float* __restrict__ Wfw,
               const float* __restrict__ Wbw)
{
    size_t e = ((size_t)blockIdx.x * 256 + threadIdx.x) * 4;
    const float4* src;
    __half* dst;
    if (e < XCNT) {
        src = (const float4*)(X + e);
        dst = g_Xh + e;
    } else {
        size_t w = e - XCNT;
        if (w < WCNT) { src = (const float4*)(Wfw + w); }
        else          { src = (const float4*)(Wbw + (w - WCNT)); }
        dst = g_Wh + w;
    }
    float4 v = *src;
    __half2 h01 = __floats2half2_rn(v.x, v.y);
    __half2 h23 = __floats2half2_rn(v.z, v.w);
    ((__half2*)dst)[0] = h01;
    ((__half2*)dst)[1] = h23;
}

// ---------------- GEMM kernel (fp16 HMMA.16816) ----------------
// grid (24 n-tiles, 128 m-tiles), 256 thr, 1 CTA/SM (96KB smem, 2-stage cp.async)
__global__ void __launch_bounds__(NTHREADS, 1)
gemm_kernel()
{
    extern __shared__ __half smem[];
    const int tid  = threadIdx.x;
    const int lane = tid & 31;
    const int wid  = tid >> 5;
    const int gid  = lane >> 2;          // 0..7
    const int tig  = lane & 3;           // 0..3
    const int warp_m = (wid >> 1) * 64;  // 0,64,128,192
    const int warp_n = (wid & 1) * 64;   // 0,64

    const int n0 = blockIdx.x * BN;      // 0..2944 over combined 3072 cols
    const int m0 = blockIdx.y * BM;

    const __half* Ag = g_Xh + (size_t)m0 * DIN;
    const __half* Bg = g_Wh + (size_t)n0 * DIN;

    char* sA0 = (char*)smem;                       // 256*64 half = 32KB
    char* sB0 = (char*)(smem + BM * BK);           // 128*64 half = 16KB
    const uint32_t sA0u = smem_u32(sA0);
    const uint32_t sB0u = smem_u32(sB0);
    const uint32_t stage_bytes = STAGE_HALFS * 2;  // 48KB

    // stage loader: A 2048 16B-chunks (8/thr), B 1024 (4/thr); 16B XOR swizzle
    auto load_stage = [&](int kt, int stage) {
        const int k0 = kt * BK;
        const uint32_t sb = stage * stage_bytes;
        #pragma unroll
        for (int i = 0; i < 8; i++) {
            int idx = tid + i * NTHREADS;
            int row = idx >> 3, c16 = idx & 7;
            uint32_t off = row * 128 + ((c16 ^ (row & 7)) << 4);
            cp_async16(sA0u + sb + off, Ag + (size_t)row * DIN + k0 + c16 * 8);
        }
        #pragma unroll
        for (int i = 0; i < 4; i++) {
            int idx = tid + i * NTHREADS;
            int row = idx >> 3, c16 = idx & 7;
            uint32_t off = row * 128 + ((c16 ^ (row & 7)) << 4);
            cp_async16(sB0u + sb + off, Bg + (size_t)row * DIN + k0 + c16 * 8);
        }
        cp_commit();
    };

    float acc[4][8][4];
    #pragma unroll
    for (int mi = 0; mi < 4; mi++)
        #pragma unroll
        for (int ni = 0; ni < 8; ni++)
            #pragma unroll
            for (int k = 0; k < 4; k++) acc[mi][ni][k] = 0.0f;

    // per-lane ldmatrix row bases (row = base + (lane&15), c16 offset = lane>>4)
    const int lrow = lane & 15;
    const int lhi  = lane >> 4;
    uint32_t a_base[4], a_key[4];
    #pragma unroll
    for (int mi = 0; mi < 4; mi++) {
        int r = warp_m + mi * 16 + lrow;
        a_base[mi] = (uint32_t)r * 128;
        a_key[mi]  = r & 7;
    }
    uint32_t b_base[4], b_key[4];
    #pragma unroll
    for (int nj = 0; nj < 4; nj++) {
        int r = warp_n + nj * 16 + lrow;
        b_base[nj] = (uint32_t)r * 128;
        b_key[nj]  = r & 7;
    }

    load_stage(0, 0);

    for (int kt = 0; kt < KTILES; kt++) {
        if (kt + 1 < KTILES) { load_stage(kt + 1, (kt + 1) & 1); cp_wait<1>(); }
        else                 { cp_wait<0>(); }
        __syncthreads();

        const uint32_t sb = (kt & 1) * stage_bytes;
        const uint32_t sAu = sA0u + sb;
        const uint32_t sBu = sB0u + sb;

        #pragma unroll
        for (int ks = 0; ks < 4; ks++) {            // k16 steps within BK=64
            const uint32_t c16 = (uint32_t)(ks * 2 + lhi);
            uint32_t a[4][4];
            #pragma unroll
            for (int mi = 0; mi < 4; mi++)
                ldsm_x4(a[mi], sAu + a_base[mi] + ((c16 ^ a_key[mi]) << 4));
            uint32_t b[4][4];
            #pragma unroll
            for (int nj = 0; nj < 4; nj++)
                ldsm_x4(b[nj], sBu + b_base[nj] + ((c16 ^ b_key[nj]) << 4));
            #pragma unroll
            for (int mi = 0; mi < 4; mi++)
                #pragma unroll
                for (int nj = 0; nj < 4; nj++) {
                    mma_f16(acc[mi][2 * nj],     a[mi], b[nj][0], b[nj][2]);
                    mma_f16(acc[mi][2 * nj + 1], a[mi], b[nj][1], b[nj][3]);
                }
        }
        __syncthreads();
    }

    // epilogue: (c0,c1) rows gid, (c2,c3) rows gid+8
    #pragma unroll
    for (int mi = 0; mi < 4; mi++) {
        int r = m0 + warp_m + mi * 16 + gid;
        #pragma unroll
        for (int ni = 0; ni < 8; ni++) {
            int c = n0 + warp_n + ni * 8 + tig * 2;
            *(float2*)(g_gates + (size_t)r * NCOLS + c) =
                make_float2(acc[mi][ni][0], acc[mi][ni][1]);
            *(float2*)(g_gates + (size_t)(r + 8) * NCOLS + c) =
                make_float2(acc[mi][ni][2], acc[mi][ni][3]);
        }
    }
}

// ---------------- activations ----------------
static __device__ __forceinline__ float fast_exp2(float x) {
    float y; asm("ex2.approx.f32 %0, %1;" : "=f"(y) : "f"(x)); return y;
}
static __device__ __forceinline__ float fast_rcp(float x) {
    float y; asm("rcp.approx.f32 %0, %1;" : "=f"(y) : "f"(x)); return y;
}
static __device__ __forceinline__ float fast_sig(float x) {
    return fast_rcp(1.0f + fast_exp2(-1.4426950408889634f * x));
}
static __device__ __forceinline__ float fast_tanh(float x) {
    return fmaf(2.0f, fast_sig(2.0f * x), -1.0f);
}

// decode channel -> pointers/biases
static __device__ __forceinline__ void ch_decode(int ch, const float* bfw, const float* bbw,
                                                 int& dir, const float*& g0, float& bz,
                                                 float& bf, float& bo, float*& o0, float* out)
{
    dir = ch >> 13;
    int c = ch & 8191;
    int b = c >> 9;
    int h = c & 511;
    const float* bias = dir ? bbw : bfw;
    bz = bias[h]; bf = bias[HID + h]; bo = bias[2 * HID + h];
    g0 = g_gates + (size_t)b * NCOLS + dir * NDIR + h;
    o0 = out ? (out + (size_t)b * (2 * HID) + dir * HID + h) : nullptr;
}

// ---- phase A: per-chunk aggregate (A = prod a, C = chunk-local h) ----
// grid 2048x128: block covers 128 consecutive channels of one chunk
__global__ void __launch_bounds__(128)
chunk_reduce(const float* __restrict__ bfw, const float* __restrict__ bbw)
{
    const int chunk = blockIdx.x >> 7;
    const int ch = ((blockIdx.x & 127) << 7) + threadIdx.x;
    int dir; const float* g0; float bz, bf, bo; float* dummy;
    ch_decode(ch, bfw, bbw, dir, g0, bz, bf, bo, dummy, nullptr);

    const int s0 = dir ? (SEQ - 1 - chunk * CHUNK) : chunk * CHUNK;
    const ptrdiff_t step = dir ? -(ptrdiff_t)GSTRIDE : (ptrdiff_t)GSTRIDE;
    const float* p = g0 + (ptrdiff_t)s0 * GSTRIDE;

    float A = 1.0f, C = 0.0f;
    #pragma unroll 4
    for (int i = 0; i < CHUNK; i++) {
        float z = fast_tanh(p[0] + bz);
        float f = fast_sig(p[HID] + bf);
        float a = 1.0f - f;
        C = fmaf(a, C, f * z);
        A *= a;
        p += step;
    }
    g_AC[chunk * NCH + ch] = make_float2(A, C);
}

// ---- phase B: scan chunk aggregates -> h at each chunk start ----
__global__ void __launch_bounds__(128)
chunk_combine()
{
    const int ch = blockIdx.x * 128 + threadIdx.x;
    float h = 0.0f;
    #pragma unroll
    for (int k = 0; k < NCHUNK; k++) {
        g_hinit[k * NCH + ch] = h;
        float2 ac = g_AC[k * NCH + ch];
        h = fmaf(ac.x, h, ac.y);
    }
}

// ---- phase C: final pass with carry-in, writes output ----
__global__ void __launch_bounds__(128)
chunk_final(const float* __restrict__ bfw, const float* __restrict__ bbw,
            float* __restrict__ out)
{
    const int chunk = blockIdx.x >> 7;
    const int ch = ((blockIdx.x & 127) << 7) + threadIdx.x;
    int dir; const float* g0; float bz, bf, bo; float* o0;
    ch_decode(ch, bfw, bbw, dir, g0, bz, bf, bo, o0, out);

    const int s0 = dir ? (SEQ - 1 - chunk * CHUNK) : chunk * CHUNK;
    const ptrdiff_t gstep = dir ? -(ptrdiff_t)GSTRIDE : (ptrdiff_t)GSTRIDE;
    const ptrdiff_t ostep = dir ? -(ptrdiff_t)OSTRIDE : (ptrdiff_t)OSTRIDE;
    const float* p = g0 + (ptrdiff_t)s0 * GSTRIDE;
    float* q = o0 + (ptrdiff_t)s0 * OSTRIDE;

    float h = g_hinit[chunk * NCH + ch];
    #pragma unroll 4
    for (int i = 0; i < CHUNK; i++) {
        float z = fast_tanh(p[0] + bz);
        float f = fast_sig(p[HID] + bf);
        float o = fast_sig(p[2 * HID] + bo);
        h = fmaf(1.0f - f, h, f * z);
        *q = o * h;
        p += gstep;
        q += ostep;
    }
}

// ---------------- launch ----------------
extern "C" void kernel_launch(void* const* d_in, const int* in_sizes, int n_in,
                              void* d_out, int out_size)
{
    (void)in_sizes; (void)n_in; (void)out_size;
    const float* X   = (const float*)d_in[0];
    const float* Wfw = (const float*)d_in[1];
    const float* bfw = (const float*)d_in[2];
    const float* Wbw = (const float*)d_in[3];
    const float* bbw = (const float*)d_in[4];
    float* out = (float*)d_out;

    cudaFuncSetAttribute(gemm_kernel,
                         cudaFuncAttributeMaxDynamicSharedMemorySize, SMEM_BYTES);

    convert_kernel<<<17920, 256>>>(X, Wfw, Wbw);
    gemm_kernel<<<dim3(24, 128), NTHREADS, SMEM_BYTES>>>();
    chunk_reduce<<<NCHUNK * 128, 128>>>(bfw, bbw);
    chunk_combine<<<NCH / 128, 128>>>();
    chunk_final<<<NCHUNK * 128, 128>>>(bfw, bbw, out);
}

// round 9
// speedup vs baseline: 2.5732x; 1.7095x over previous
#include <cuda_runtime.h>
#include <cuda_fp16.h>
#include <cstdint>
#include <cstddef>

// ---------------- problem constants ----------------
#define SEQ   2048
#define BATCH 16
#define DIN   512
#define HID   512
#define MROWS (SEQ*BATCH)      // 32768 rows (s*16+b)
#define NDIR  (3*HID)          // 1536 gate cols per direction
#define NCOLS (2*NDIR)         // 3072 combined
#define XCNT  ((size_t)MROWS*DIN)

// ---------------- GEMM tiling (fp16 mma m16n8k16, fused epilogue) ----------------
#define BM 128
#define BN 96                  // 32 h * 3 gates (z,f,o interleaved)
#define BK 64                  // halves per k-tile (128B rows)
#define KTILES (DIN/BK)        // 8
#define NTHREADS 256
#define STAGE_BYTES ((BM+BN)*BK*2)            // 28672
#define SMEM_BYTES  (2*STAGE_BYTES)           // 57344 (epilogue reuse: 128*100*4=51200)
#define EPIPITCH 100

// ---------------- scan chunking ----------------
#define NCH    16384           // dir*8192 + b*512 + h
#define CHUNK  128
#define NCHUNK (SEQ/CHUNK)     // 16
#define ACSTRIDE (BATCH*2*HID) // per-s stride in g_ac/g_o elements (16384)

// ---------------- device scratch ----------------
__device__ __half  g_Xh[XCNT];                       // fp16 X (67MB... 33.5M halfs)
__device__ __half  g_Wh[(size_t)NCOLS * DIN];        // fp16 permuted [dir][h*3+g]
__device__ __half2 g_ac[(size_t)MROWS * 2 * HID];    // (a=1-f, c=f*z) per (s,b,dir,h)
__device__ __half  g_o[(size_t)MROWS * 2 * HID];     // o gate
__device__ float2  g_AC[NCH * NCHUNK];               // per-chunk (A, C)
__device__ float   g_hinit[NCH * NCHUNK];            // h at chunk start

// ---------------- helpers ----------------
static __device__ __forceinline__ uint32_t smem_u32(const void* p) {
    uint32_t a;
    asm("{ .reg .u64 t; cvta.to.shared.u64 t, %1; cvt.u32.u64 %0, t; }"
        : "=r"(a) : "l"(p));
    return a;
}
static __device__ __forceinline__ void cp_async16(uint32_t saddr, const void* gaddr) {
    asm volatile("cp.async.ca.shared.global [%0], [%1], 16;"
                 :: "r"(saddr), "l"(gaddr) : "memory");
}
static __device__ __forceinline__ void cp_commit() {
    asm volatile("cp.async.commit_group;" ::: "memory");
}
template <int N>
static __device__ __forceinline__ void cp_wait() {
    asm volatile("cp.async.wait_group %0;" :: "n"(N) : "memory");
}
static __device__ __forceinline__ void ldsm_x4(uint32_t* r, uint32_t addr) {
    asm volatile("ldmatrix.sync.aligned.m8n8.x4.shared.b16 {%0,%1,%2,%3}, [%4];"
                 : "=r"(r[0]), "=r"(r[1]), "=r"(r[2]), "=r"(r[3]) : "r"(addr));
}
static __device__ __forceinline__ void mma_f16(float* d, const uint32_t* a,
                                               uint32_t b0, uint32_t b1) {
    asm volatile(
        "mma.sync.aligned.m16n8k16.row.col.f32.f16.f16.f32 "
        "{%0,%1,%2,%3}, {%4,%5,%6,%7}, {%8,%9}, {%0,%1,%2,%3};"
        : "+f"(d[0]), "+f"(d[1]), "+f"(d[2]), "+f"(d[3])
        : "r"(a[0]), "r"(a[1]), "r"(a[2]), "r"(a[3]), "r"(b0), "r"(b1));
}
static __device__ __forceinline__ float fast_exp2(float x) {
    float y; asm("ex2.approx.f32 %0, %1;" : "=f"(y) : "f"(x)); return y;
}
static __device__ __forceinline__ float fast_rcp(float x) {
    float y; asm("rcp.approx.f32 %0, %1;" : "=f"(y) : "f"(x)); return y;
}
static __device__ __forceinline__ float fast_sig(float x) {
    return fast_rcp(1.0f + fast_exp2(-1.4426950408889634f * x));
}
static __device__ __forceinline__ float fast_tanh(float x) {
    return fmaf(2.0f, fast_sig(2.0f * x), -1.0f);
}

// ---------------- fp32 -> fp16 pre-convert (+ W gate-interleave permute) ----------------
// blocks [0,16384): X vec4 copy. blocks [16384,17920): W permute, 2 rows/block.
__global__ void __launch_bounds__(256)
convert_kernel(const float* __restrict__ X,
               const float* __restrict__ Wfw,
               const float* __restrict__ Wbw)
{
    const int tid = threadIdx.x;
    if (blockIdx.x < 16384) {
        size_t e = ((size_t)blockIdx.x * 256 + tid) * 4;
        float4 v = *(const float4*)(X + e);
        __half* dst = g_Xh + e;
        ((__half2*)dst)[0] = __floats2half2_rn(v.x, v.y);
        ((__half2*)dst)[1] = __floats2half2_rn(v.z, v.w);
    } else {
        int blk2 = blockIdx.x - 16384;                 // 0..1535
        int wrow = blk2 * 2 + (tid >> 7);              // dest row 0..3071
        int j    = (tid & 127) * 4;                    // float offset in row
        int dir = wrow / NDIR;
        int rem = wrow % NDIR;
        int h = rem / 3, g = rem % 3;
        const float* src = (dir ? Wbw : Wfw) + ((size_t)(g * HID + h)) * DIN + j;
        float4 v = *(const float4*)src;
        __half* dst = g_Wh + (size_t)wrow * DIN + j;
        ((__half2*)dst)[0] = __floats2half2_rn(v.x, v.y);
        ((__half2*)dst)[1] = __floats2half2_rn(v.z, v.w);
    }
}

// ---------------- GEMM kernel (fp16 HMMA + fused activation epilogue) ----------------
// grid (32 n-tiles, 256 m-tiles), 256 thr, 2 CTA/SM
__global__ void __launch_bounds__(NTHREADS, 2)
gemm_kernel(const float* __restrict__ bfw, const float* __restrict__ bbw)
{
    extern __shared__ __half smem[];
    const int tid  = threadIdx.x;
    const int lane = tid & 31;
    const int wid  = tid >> 5;
    const int gid  = lane >> 2;            // 0..7
    const int tig  = lane & 3;             // 0..3
    const int warp_m = (wid >> 1) * 32;    // 0,32,64,96
    const int warp_n = (wid & 1) * 48;     // 0,48

    const int n0 = blockIdx.x * BN;        // multiple of 96; within one dir
    const int m0 = blockIdx.y * BM;

    const __half* Ag = g_Xh + (size_t)m0 * DIN;
    const __half* Bg = g_Wh + (size_t)n0 * DIN;

    const uint32_t sA0u = smem_u32(smem);                      // A: 128*64 half = 16KB
    const uint32_t sB0u = sA0u + BM * BK * 2;                  // B: 96*64 half = 12KB

    auto load_stage = [&](int kt, int stage) {
        const int k0 = kt * BK;
        const uint32_t sb = stage * STAGE_BYTES;
        #pragma unroll
        for (int i = 0; i < 4; i++) {                          // A: 1024 chunks
            int idx = tid + i * NTHREADS;
            int row = idx >> 3, c16 = idx & 7;
            uint32_t off = row * 128 + ((c16 ^ (row & 7)) << 4);
            cp_async16(sA0u + sb + off, Ag + (size_t)row * DIN + k0 + c16 * 8);
        }
        #pragma unroll
        for (int i = 0; i < 3; i++) {                          // B: 768 chunks
            int idx = tid + i * NTHREADS;
            int row = idx >> 3, c16 = idx & 7;
            uint32_t off = row * 128 + ((c16 ^ (row & 7)) << 4);
            cp_async16(sB0u + sb + off, Bg + (size_t)row * DIN + k0 + c16 * 8);
        }
        cp_commit();
    };

    float acc[2][6][4];
    #pragma unroll
    for (int mi = 0; mi < 2; mi++)
        #pragma unroll
        for (int ni = 0; ni < 6; ni++)
            #pragma unroll
            for (int k = 0; k < 4; k++) acc[mi][ni][k] = 0.0f;

    const int lrow = lane & 15;
    const int lhi  = lane >> 4;
    uint32_t a_base[2], a_key[2];
    #pragma unroll
    for (int mi = 0; mi < 2; mi++) {
        int r = warp_m + mi * 16 + lrow;
        a_base[mi] = (uint32_t)r * 128;
        a_key[mi]  = r & 7;
    }
    uint32_t b_base[3], b_key[3];
    #pragma unroll
    for (int nj = 0; nj < 3; nj++) {
        int r = warp_n + nj * 16 + lrow;
        b_base[nj] = (uint32_t)r * 128;
        b_key[nj]  = r & 7;
    }

    load_stage(0, 0);

    for (int kt = 0; kt < KTILES; kt++) {
        if (kt + 1 < KTILES) { load_stage(kt + 1, (kt + 1) & 1); cp_wait<1>(); }
        else                 { cp_wait<0>(); }
        __syncthreads();

        const uint32_t sb = (kt & 1) * STAGE_BYTES;
        const uint32_t sAu = sA0u + sb;
        const uint32_t sBu = sB0u + sb;

        #pragma unroll
        for (int ks = 0; ks < 4; ks++) {
            const uint32_t c16 = (uint32_t)(ks * 2 + lhi);
            uint32_t a[2][4];
            #pragma unroll
            for (int mi = 0; mi < 2; mi++)
                ldsm_x4(a[mi], sAu + a_base[mi] + ((c16 ^ a_key[mi]) << 4));
            uint32_t b[3][4];
            #pragma unroll
            for (int nj = 0; nj < 3; nj++)
                ldsm_x4(b[nj], sBu + b_base[nj] + ((c16 ^ b_key[nj]) << 4));
            #pragma unroll
            for (int mi = 0; mi < 2; mi++)
                #pragma unroll
                for (int nj = 0; nj < 3; nj++) {
                    mma_f16(acc[mi][2 * nj],     a[mi], b[nj][0], b[nj][2]);
                    mma_f16(acc[mi][2 * nj + 1], a[mi], b[nj][1], b[nj][3]);
                }
        }
        __syncthreads();
    }

    // ---- fused epilogue: stage accs through smem, combine z,f,o per h ----
    float* sred = (float*)smem;                  // 128 x 100 pitch = 51.2KB
    #pragma unroll
    for (int mi = 0; mi < 2; mi++) {
        int r0 = warp_m + mi * 16 + gid;
        #pragma unroll
        for (int ni = 0; ni < 6; ni++) {
            int cl = warp_n + ni * 8 + tig * 2;
            *(float2*)(sred + r0 * EPIPITCH + cl) =
                make_float2(acc[mi][ni][0], acc[mi][ni][1]);
            *(float2*)(sred + (r0 + 8) * EPIPITCH + cl) =
                make_float2(acc[mi][ni][2], acc[mi][ni][3]);
        }
    }
    __syncthreads();

    const int dir   = n0 / NDIR;
    const int hg    = (n0 % NDIR) / 3 + lane;    // global h for this lane
    const float* bias = dir ? bbw : bfw;
    const float bz = bias[hg];
    const float bf = bias[HID + hg];
    const float bo = bias[2 * HID + hg];

    #pragma unroll 4
    for (int i = 0; i < 16; i++) {
        int row = wid + i * 8;                   // 0..127
        const float* rp = sred + row * EPIPITCH + lane * 3;
        float z = fast_tanh(rp[0] + bz);
        float f = fast_sig(rp[1] + bf);
        float o = fast_sig(rp[2] + bo);
        size_t idx = ((size_t)(m0 + row) * 2 + dir) * HID + hg;
        g_ac[idx] = __floats2half2_rn(1.0f - f, f * z);   // (.x=a, .y=c)
        g_o[idx]  = __float2half_rn(o);
    }
}

// ---------------- scan phases ----------------
// ch = dir*8192 + b*512 + h; element index for (s,b,dir,h):
//   idx = ((s*16+b)*2 + dir)*512 + h ; per-s stride = 16384

// ---- phase A: per-chunk (A = prod a, C = chunk-local h); no MUFU ----
__global__ void __launch_bounds__(128)
chunk_reduce()
{
    const int chunk = blockIdx.x >> 7;
    const int ch = ((blockIdx.x & 127) << 7) + threadIdx.x;
    const int dir = ch >> 13;
    const int b   = (ch >> 9) & 15;
    const int h   = ch & 511;
    const int s0  = dir ? (SEQ - 1 - chunk * CHUNK) : chunk * CHUNK;
    const ptrdiff_t step = dir ? -(ptrdiff_t)ACSTRIDE : (ptrdiff_t)ACSTRIDE;

    const __half2* p = g_ac + ((size_t)(s0 * BATCH + b) * 2 + dir) * HID + h;

    float A = 1.0f, C = 0.0f;
    #pragma unroll 8
    for (int i = 0; i < CHUNK; i++) {
        float2 v = __half22float2(*p);
        C = fmaf(v.x, C, v.y);
        A *= v.x;
        p += step;
    }
    g_AC[chunk * NCH + ch] = make_float2(A, C);
}

// ---- phase B: scan chunk aggregates -> h at each chunk start ----
__global__ void __launch_bounds__(128)
chunk_combine()
{
    const int ch = blockIdx.x * 128 + threadIdx.x;
    float h = 0.0f;
    #pragma unroll
    for (int k = 0; k < NCHUNK; k++) {
        g_hinit[k * NCH + ch] = h;
        float2 ac = g_AC[k * NCH + ch];
        h = fmaf(ac.x, h, ac.y);
    }
}

// ---- phase C: final pass with carry-in, writes output ----
__global__ void __launch_bounds__(128)
chunk_final(float* __restrict__ out)
{
    const int chunk = blockIdx.x >> 7;
    const int ch = ((blockIdx.x & 127) << 7) + threadIdx.x;
    const int dir = ch >> 13;
    const int b   = (ch >> 9) & 15;
    const int hh  = ch & 511;
    const int s0  = dir ? (SEQ - 1 - chunk * CHUNK) : chunk * CHUNK;
    const ptrdiff_t step = dir ? -(ptrdiff_t)ACSTRIDE : (ptrdiff_t)ACSTRIDE;

    const size_t base = ((size_t)(s0 * BATCH + b) * 2 + dir) * HID + hh;
    const __half2* p = g_ac + base;
    const __half*  po = g_o + base;
    float* q = out + (size_t)s0 * (BATCH * 2 * HID) + (size_t)b * (2 * HID) + dir * HID + hh;
    const ptrdiff_t ostep = dir ? -(ptrdiff_t)(BATCH * 2 * HID) : (ptrdiff_t)(BATCH * 2 * HID);

    float h = g_hinit[chunk * NCH + ch];
    #pragma unroll 8
    for (int i = 0; i < CHUNK; i++) {
        float2 v = __half22float2(*p);
        float o  = __half2float(*po);
        h = fmaf(v.x, h, v.y);
        *q = o * h;
        p += step; po += step; q += ostep;
    }
}

// ---------------- launch ----------------
extern "C" void kernel_launch(void* const* d_in, const int* in_sizes, int n_in,
                              void* d_out, int out_size)
{
    (void)in_sizes; (void)n_in; (void)out_size;
    const float* X   = (const float*)d_in[0];
    const float* Wfw = (const float*)d_in[1];
    const float* bfw = (const float*)d_in[2];
    const float* Wbw = (const float*)d_in[3];
    const float* bbw = (const float*)d_in[4];
    float* out = (float*)d_out;

    cudaFuncSetAttribute(gemm_kernel,
                         cudaFuncAttributeMaxDynamicSharedMemorySize, SMEM_BYTES);

    convert_kernel<<<17920, 256>>>(X, Wfw, Wbw);
    gemm_kernel<<<dim3(32, 256), NTHREADS, SMEM_BYTES>>>(bfw, bbw);
    chunk_reduce<<<NCHUNK * 128, 128>>>();
    chunk_combine<<<NCH / 128, 128>>>();
    chunk_final<<<NCHUNK * 128, 128>>>(out);
}

// round 12
// speedup vs baseline: 2.6252x; 1.0202x over previous
#include <cuda_runtime.h>
#include <cuda_fp16.h>
#include <cstdint>
#include <cstddef>

// ---------------- problem constants ----------------
#define SEQ   2048
#define BATCH 16
#define DIN   512
#define HID   512
#define MROWS (SEQ*BATCH)      // 32768 rows (s*16+b)
#define NDIR  (3*HID)          // 1536 gate cols per direction
#define NCOLS (2*NDIR)         // 3072 combined
#define XCNT  ((size_t)MROWS*DIN)

// ---------------- GEMM tiling (fp16 mma m16n8k16, fused epilogue) ----------------
#define BM 128
#define BN 192                 // 64 h * 3 gates (z,f,o interleaved)
#define BK 64                  // halves per k-tile (128B rows)
#define KTILES (DIN/BK)        // 8
#define NTHREADS 512
#define NSTAGE 3
#define STAGE_BYTES ((BM+BN)*BK*2)            // 40960
#define SMEM_BYTES  (NSTAGE*STAGE_BYTES)      // 122880 (epilogue reuse 128*196*4=100352)
#define EPIPITCH 196

// ---------------- scan chunking ----------------
#define NCH    16384           // dir*8192 + b*512 + h
#define CHUNK  128
#define NCHUNK (SEQ/CHUNK)     // 16
#define ACSTRIDE (BATCH*2*HID) // per-s stride in g_ac/g_o elements (16384)

// ---------------- device scratch ----------------
__device__ __half  g_Xh[XCNT];                       // fp16 X
__device__ __half  g_Wh[(size_t)NCOLS * DIN];        // fp16 permuted [dir][h*3+g]
__device__ __half2 g_ac[(size_t)MROWS * 2 * HID];    // (a=1-f, c=f*z)
__device__ __half  g_o[(size_t)MROWS * 2 * HID];     // o gate
__device__ float2  g_AC[NCH * NCHUNK];               // per-chunk (A,C), [ch][chunk]

// ---------------- helpers ----------------
static __device__ __forceinline__ uint32_t smem_u32(const void* p) {
    uint32_t a;
    asm("{ .reg .u64 t; cvta.to.shared.u64 t, %1; cvt.u32.u64 %0, t; }"
        : "=r"(a) : "l"(p));
    return a;
}
static __device__ __forceinline__ void cp_async16(uint32_t saddr, const void* gaddr) {
    asm volatile("cp.async.cg.shared.global [%0], [%1], 16;"
                 :: "r"(saddr), "l"(gaddr) : "memory");
}
static __device__ __forceinline__ void cp_commit() {
    asm volatile("cp.async.commit_group;" ::: "memory");
}
template <int N>
static __device__ __forceinline__ void cp_wait() {
    asm volatile("cp.async.wait_group %0;" :: "n"(N) : "memory");
}
static __device__ __forceinline__ void ldsm_x4(uint32_t* r, uint32_t addr) {
    asm volatile("ldmatrix.sync.aligned.m8n8.x4.shared.b16 {%0,%1,%2,%3}, [%4];"
                 : "=r"(r[0]), "=r"(r[1]), "=r"(r[2]), "=r"(r[3]) : "r"(addr));
}
static __device__ __forceinline__ void mma_f16(float* d, const uint32_t* a,
                                               uint32_t b0, uint32_t b1) {
    asm volatile(
        "mma.sync.aligned.m16n8k16.row.col.f32.f16.f16.f32 "
        "{%0,%1,%2,%3}, {%4,%5,%6,%7}, {%8,%9}, {%0,%1,%2,%3};"
        : "+f"(d[0]), "+f"(d[1]), "+f"(d[2]), "+f"(d[3])
        : "r"(a[0]), "r"(a[1]), "r"(a[2]), "r"(a[3]), "r"(b0), "r"(b1));
}
static __device__ __forceinline__ float fast_exp2(float x) {
    float y; asm("ex2.approx.f32 %0, %1;" : "=f"(y) : "f"(x)); return y;
}
static __device__ __forceinline__ float fast_rcp(float x) {
    float y; asm("rcp.approx.f32 %0, %1;" : "=f"(y) : "f"(x)); return y;
}
static __device__ __forceinline__ float fast_sig(float x) {
    return fast_rcp(1.0f + fast_exp2(-1.4426950408889634f * x));
}
static __device__ __forceinline__ float fast_tanh(float x) {
    return fmaf(2.0f, fast_sig(2.0f * x), -1.0f);
}

// ---------------- fp32 -> fp16 pre-convert (+ W gate-interleave permute) ----------------
// blocks [0,16384): X vec4 copy. blocks [16384,17920): W permute, 2 rows/block.
__global__ void __launch_bounds__(256)
convert_kernel(const float* __restrict__ X,
               const float* __restrict__ Wfw,
               const float* __restrict__ Wbw)
{
    const int tid = threadIdx.x;
    if (blockIdx.x < 16384) {
        size_t e = ((size_t)blockIdx.x * 256 + tid) * 4;
        float4 v = *(const float4*)(X + e);
        __half* dst = g_Xh + e;
        ((__half2*)dst)[0] = __floats2half2_rn(v.x, v.y);
        ((__half2*)dst)[1] = __floats2half2_rn(v.z, v.w);
    } else {
        int blk2 = blockIdx.x - 16384;                 // 0..1535
        int wrow = blk2 * 2 + (tid >> 7);              // dest row 0..3071
        int j    = (tid & 127) * 4;
        int dir = wrow / NDIR;
        int rem = wrow % NDIR;
        int h = rem / 3, g = rem % 3;
        const float* src = (dir ? Wbw : Wfw) + ((size_t)(g * HID + h)) * DIN + j;
        float4 v = *(const float4*)src;
        __half* dst = g_Wh + (size_t)wrow * DIN + j;
        ((__half2*)dst)[0] = __floats2half2_rn(v.x, v.y);
        ((__half2*)dst)[1] = __floats2half2_rn(v.z, v.w);
    }
}

// ---------------- GEMM kernel (fp16 HMMA + fused activation epilogue) ----------------
// grid (16 n-tiles, 256 m-tiles), 512 thr, 1 CTA/SM, 3-stage cp.async
__global__ void __launch_bounds__(NTHREADS, 1)
gemm_kernel(const float* __restrict__ bfw, const float* __restrict__ bbw)
{
    extern __shared__ __half smem[];
    const int tid  = threadIdx.x;
    const int lane = tid & 31;
    const int wid  = tid >> 5;                 // 0..15
    const int gid  = lane >> 2;                // 0..7
    const int tig  = lane & 3;                 // 0..3
    const int warp_m = (wid >> 2) * 32;        // 0,32,64,96
    const int warp_n = (wid & 3) * 48;         // 0,48,96,144

    const int n0 = blockIdx.x * BN;            // multiple of 192; within one dir
    const int m0 = blockIdx.y * BM;

    const __half* Ag = g_Xh + (size_t)m0 * DIN;
    const __half* Bg = g_Wh + (size_t)n0 * DIN;

    const uint32_t sbase = smem_u32(smem);
    // per stage: A at +0 (128*128B=16KB), B at +16KB (192*128B=24KB)

    auto load_stage = [&](int kt) {
        const int k0 = kt * BK;
        const uint32_t sb = sbase + (kt % NSTAGE) * STAGE_BYTES;
        #pragma unroll
        for (int i = 0; i < 2; i++) {                          // A: 1024 chunks
            int idx = tid + i * NTHREADS;
            int row = idx >> 3, c16 = idx & 7;
            uint32_t off = row * 128 + ((c16 ^ (row & 7)) << 4);
            cp_async16(sb + off, Ag + (size_t)row * DIN + k0 + c16 * 8);
        }
        #pragma unroll
        for (int i = 0; i < 3; i++) {                          // B: 1536 chunks
            int idx = tid + i * NTHREADS;
            int row = idx >> 3, c16 = idx & 7;
            uint32_t off = BM * 128 + row * 128 + ((c16 ^ (row & 7)) << 4);
            cp_async16(sb + off, Bg + (size_t)row * DIN + k0 + c16 * 8);
        }
        cp_commit();
    };

    float acc[2][6][4];
    #pragma unroll
    for (int mi = 0; mi < 2; mi++)
        #pragma unroll
        for (int ni = 0; ni < 6; ni++)
            #pragma unroll
            for (int k = 0; k < 4; k++) acc[mi][ni][k] = 0.0f;

    const int lrow = lane & 15;
    const int lhi  = lane >> 4;
    uint32_t a_base[2], a_key[2];
    #pragma unroll
    for (int mi = 0; mi < 2; mi++) {
        int r = warp_m + mi * 16 + lrow;
        a_base[mi] = (uint32_t)r * 128;
        a_key[mi]  = r & 7;
    }
    uint32_t b_base[3], b_key[3];
    #pragma unroll
    for (int nj = 0; nj < 3; nj++) {
        int r = warp_n + nj * 16 + lrow;
        b_base[nj] = BM * 128 + (uint32_t)r * 128;
        b_key[nj]  = r & 7;
    }

    load_stage(0);
    load_stage(1);

    for (int kt = 0; kt < KTILES; kt++) {
        if (kt + 2 < KTILES) { load_stage(kt + 2); cp_wait<2>(); }
        else if (kt + 2 == KTILES) { cp_wait<1>(); }
        else { cp_wait<0>(); }
        __syncthreads();

        const uint32_t sb = sbase + (kt % NSTAGE) * STAGE_BYTES;

        #pragma unroll
        for (int ks = 0; ks < 4; ks++) {
            const uint32_t c16 = (uint32_t)(ks * 2 + lhi);
            uint32_t a[2][4];
            #pragma unroll
            for (int mi = 0; mi < 2; mi++)
                ldsm_x4(a[mi], sb + a_base[mi] + ((c16 ^ a_key[mi]) << 4));
            uint32_t b[3][4];
            #pragma unroll
            for (int nj = 0; nj < 3; nj++)
                ldsm_x4(b[nj], sb + b_base[nj] + ((c16 ^ b_key[nj]) << 4));
            #pragma unroll
            for (int mi = 0; mi < 2; mi++)
                #pragma unroll
                for (int nj = 0; nj < 3; nj++) {
                    mma_f16(acc[mi][2 * nj],     a[mi], b[nj][0], b[nj][2]);
                    mma_f16(acc[mi][2 * nj + 1], a[mi], b[nj][1], b[nj][3]);
                }
        }
        __syncthreads();
    }

    // ---- fused epilogue: stage accs through smem, combine z,f,o per h ----
    float* sred = (float*)smem;                  // 128 x 196 pitch = 100KB
    #pragma unroll
    for (int mi = 0; mi < 2; mi++) {
        int r0 = warp_m + mi * 16 + gid;
        #pragma unroll
        for (int ni = 0; ni < 6; ni++) {
            int cl = warp_n + ni * 8 + tig * 2;
            *(float2*)(sred + r0 * EPIPITCH + cl) =
                make_float2(acc[mi][ni][0], acc[mi][ni][1]);
            *(float2*)(sred + (r0 + 8) * EPIPITCH + cl) =
                make_float2(acc[mi][ni][2], acc[mi][ni][3]);
        }
    }
    __syncthreads();

    // thread t handles h_local = t&63 (fixed bias), rows (t>>6) + 8*i
    const int hl = tid & 63;
    const int rg = tid >> 6;                     // 0..7
    const int dir = n0 / NDIR;
    const int hg  = (n0 % NDIR) / 3 + hl;
    const float* bias = dir ? bbw : bfw;
    const float bz = bias[hg];
    const float bf = bias[HID + hg];
    const float bo = bias[2 * HID + hg];

    #pragma unroll 4
    for (int i = 0; i < 16; i++) {
        int row = rg + i * 8;                    // 0..127
        const float* rp = sred + row * EPIPITCH + hl * 3;
        float z = fast_tanh(rp[0] + bz);
        float f = fast_sig(rp[1] + bf);
        float o = fast_sig(rp[2] + bo);
        size_t idx = ((size_t)(m0 + row) * 2 + dir) * HID + hg;
        g_ac[idx] = __floats2half2_rn(1.0f - f, f * z);   // (.x=a, .y=c)
        g_o[idx]  = __float2half_rn(o);
    }
}

// ---------------- scan phases ----------------
// ch = dir*8192 + b*512 + h; element index for (s,b,dir,h):
//   idx = ((s*16+b)*2 + dir)*512 + h ; per-s stride = 16384

// ---- phase A: per-chunk (A = prod a, C = chunk-local h) ----
__global__ void __launch_bounds__(128)
chunk_reduce()
{
    const int chunk = blockIdx.x >> 7;
    const int ch = ((blockIdx.x & 127) << 7) + threadIdx.x;
    const int dir = ch >> 13;
    const int b   = (ch >> 9) & 15;
    const int h   = ch & 511;
    const int s0  = dir ? (SEQ - 1 - chunk * CHUNK) : chunk * CHUNK;
    const ptrdiff_t step = dir ? -(ptrdiff_t)ACSTRIDE : (ptrdiff_t)ACSTRIDE;

    const __half2* p = g_ac + ((size_t)(s0 * BATCH + b) * 2 + dir) * HID + h;

    float A = 1.0f, C = 0.0f;
    #pragma unroll 8
    for (int i = 0; i < CHUNK; i++) {
        float2 v = __half22float2(*p);
        C = fmaf(v.x, C, v.y);
        A *= v.x;
        p += step;
    }
    g_AC[(size_t)ch * NCHUNK + chunk] = make_float2(A, C);
}

// ---- phase C: inline carry combine + final pass, writes output ----
__global__ void __launch_bounds__(128)
chunk_final(float* __restrict__ out)
{
    const int chunk = blockIdx.x >> 7;
    const int ch = ((blockIdx.x & 127) << 7) + threadIdx.x;
    const int dir = ch >> 13;
    const int b   = (ch >> 9) & 15;
    const int hh  = ch & 511;
    const int s0  = dir ? (SEQ - 1 - chunk * CHUNK) : chunk * CHUNK;
    const ptrdiff_t step = dir ? -(ptrdiff_t)ACSTRIDE : (ptrdiff_t)ACSTRIDE;

    // carry-in: scan the preceding chunk aggregates (contiguous per channel)
    float h = 0.0f;
    const float2* acp = g_AC + (size_t)ch * NCHUNK;
    for (int k = 0; k < chunk; k++) {
        float2 ac = acp[k];
        h = fmaf(ac.x, h, ac.y);
    }

    const size_t base = ((size_t)(s0 * BATCH + b) * 2 + dir) * HID + hh;
    const __half2* p = g_ac + base;
    const __half*  po = g_o + base;
    float* q = out + (size_t)s0 * (BATCH * 2 * HID) + (size_t)b * (2 * HID) + dir * HID + hh;
    const ptrdiff_t ostep = dir ? -(ptrdiff_t)(BATCH * 2 * HID) : (ptrdiff_t)(BATCH * 2 * HID);

    #pragma unroll 8
    for (int i = 0; i < CHUNK; i++) {
        float2 v = __half22float2(*p);
        float o  = __half2float(*po);
        h = fmaf(v.x, h, v.y);
        *q = o * h;
        p += step; po += step; q += ostep;
    }
}

// ---------------- launch ----------------
extern "C" void kernel_launch(void* const* d_in, const int* in_sizes, int n_in,
                              void* d_out, int out_size)
{
    (void)in_sizes; (void)n_in; (void)out_size;
    const float* X   = (const float*)d_in[0];
    const float* Wfw = (const float*)d_in[1];
    const float* bfw = (const float*)d_in[2];
    const float* Wbw = (const float*)d_in[3];
    const float* bbw = (const float*)d_in[4];
    float* out = (float*)d_out;

    cudaFuncSetAttribute(gemm_kernel,
                         cudaFuncAttributeMaxDynamicSharedMemorySize, SMEM_BYTES);

    convert_kernel<<<17920, 256>>>(X, Wfw, Wbw);
    gemm_kernel<<<dim3(16, 256), NTHREADS, SMEM_BYTES>>>(bfw, bbw);
    chunk_reduce<<<NCHUNK * 128, 128>>>();
    chunk_final<<<NCHUNK * 128, 128>>>(out);
}

// round 13
// speedup vs baseline: 2.8179x; 1.0734x over previous
#include <cuda_runtime.h>
#include <cuda_fp16.h>
#include <cstdint>
#include <cstddef>

// ---------------- problem constants ----------------
#define SEQ   2048
#define BATCH 16
#define DIN   512
#define HID   512
#define MROWS (SEQ*BATCH)      // 32768 rows (s*16+b)
#define NDIR  (3*HID)          // 1536 gate cols per direction
#define NCOLS (2*NDIR)         // 3072 combined
#define XCNT  ((size_t)MROWS*DIN)

// ---------------- GEMM tiling (fp16 mma m16n8k16, fused epilogue+scan) ----------------
#define BM 128                 // = 8 seq steps x 16 batch
#define BN 96                  // 32 h * 3 gates (z,f,o interleaved)
#define BK 64                  // halves per k-tile (128B rows)
#define KTILES (DIN/BK)        // 8
#define NTHREADS 256
#define NSTAGE 3
#define STAGE_BYTES ((BM+BN)*BK*2)            // 28672
#define SMEM_BYTES  (NSTAGE*STAGE_BYTES)      // 86016 (epilogue reuse 128*100*4=51200)
#define EPIPITCH 100

// ---------------- scan chunking ----------------
#define NCH     16384          // dir*8192 + b*512 + h
#define NCHUNK  256            // chunks of 8 steps (one per m-tile)
#define NSUPER  16             // superchunks of 16 chunks (128 steps)

// ---------------- device scratch ----------------
__device__ __half  g_Xh[XCNT];                       // fp16 X
__device__ __half  g_Wh[(size_t)NCOLS * DIN];        // fp16 permuted [dir][h*3+g]
__device__ __half2 g_ph[(size_t)MROWS * 2 * HID];    // (P=prefix prod a, H=local h)
__device__ __half  g_o[(size_t)MROWS * 2 * HID];     // o gate
__device__ float2  g_AC[(size_t)NCH * NCHUNK];       // per-chunk (A,C), [ch][chunk]
__device__ float   g_hsup[(size_t)NCH * NSUPER];     // h at superchunk start

// ---------------- helpers ----------------
static __device__ __forceinline__ uint32_t smem_u32(const void* p) {
    uint32_t a;
    asm("{ .reg .u64 t; cvta.to.shared.u64 t, %1; cvt.u32.u64 %0, t; }"
        : "=r"(a) : "l"(p));
    return a;
}
static __device__ __forceinline__ void cp_async16(uint32_t saddr, const void* gaddr) {
    asm volatile("cp.async.cg.shared.global [%0], [%1], 16;"
                 :: "r"(saddr), "l"(gaddr) : "memory");
}
static __device__ __forceinline__ void cp_commit() {
    asm volatile("cp.async.commit_group;" ::: "memory");
}
template <int N>
static __device__ __forceinline__ void cp_wait() {
    asm volatile("cp.async.wait_group %0;" :: "n"(N) : "memory");
}
static __device__ __forceinline__ void ldsm_x4(uint32_t* r, uint32_t addr) {
    asm volatile("ldmatrix.sync.aligned.m8n8.x4.shared.b16 {%0,%1,%2,%3}, [%4];"
                 : "=r"(r[0]), "=r"(r[1]), "=r"(r[2]), "=r"(r[3]) : "r"(addr));
}
static __device__ __forceinline__ void mma_f16(float* d, const uint32_t* a,
                                               uint32_t b0, uint32_t b1) {
    asm volatile(
        "mma.sync.aligned.m16n8k16.row.col.f32.f16.f16.f32 "
        "{%0,%1,%2,%3}, {%4,%5,%6,%7}, {%8,%9}, {%0,%1,%2,%3};"
        : "+f"(d[0]), "+f"(d[1]), "+f"(d[2]), "+f"(d[3])
        : "r"(a[0]), "r"(a[1]), "r"(a[2]), "r"(a[3]), "r"(b0), "r"(b1));
}
static __device__ __forceinline__ float fast_exp2(float x) {
    float y; asm("ex2.approx.f32 %0, %1;" : "=f"(y) : "f"(x)); return y;
}
static __device__ __forceinline__ float fast_rcp(float x) {
    float y; asm("rcp.approx.f32 %0, %1;" : "=f"(y) : "f"(x)); return y;
}
static __device__ __forceinline__ float fast_sig(float x) {
    return fast_rcp(1.0f + fast_exp2(-1.4426950408889634f * x));
}
static __device__ __forceinline__ float fast_tanh(float x) {
    return fmaf(2.0f, fast_sig(2.0f * x), -1.0f);
}

// ---------------- fp32 -> fp16 pre-convert (+ W gate-interleave permute) ----------------
// blocks [0,16384): X vec4 copy. blocks [16384,17920): W permute, 2 rows/block.
__global__ void __launch_bounds__(256)
convert_kernel(const float* __restrict__ X,
               const float* __restrict__ Wfw,
               const float* __restrict__ Wbw)
{
    const int tid = threadIdx.x;
    if (blockIdx.x < 16384) {
        size_t e = ((size_t)blockIdx.x * 256 + tid) * 4;
        float4 v = *(const float4*)(X + e);
        __half* dst = g_Xh + e;
        ((__half2*)dst)[0] = __floats2half2_rn(v.x, v.y);
        ((__half2*)dst)[1] = __floats2half2_rn(v.z, v.w);
    } else {
        int blk2 = blockIdx.x - 16384;                 // 0..1535
        int wrow = blk2 * 2 + (tid >> 7);              // dest row 0..3071
        int j    = (tid & 127) * 4;
        int dir = wrow / NDIR;
        int rem = wrow % NDIR;
        int h = rem / 3, g = rem % 3;
        const float* src = (dir ? Wbw : Wfw) + ((size_t)(g * HID + h)) * DIN + j;
        float4 v = *(const float4*)src;
        __half* dst = g_Wh + (size_t)wrow * DIN + j;
        ((__half2*)dst)[0] = __floats2half2_rn(v.x, v.y);
        ((__half2*)dst)[1] = __floats2half2_rn(v.z, v.w);
    }
}

// ---------------- GEMM kernel (fp16 HMMA + fused activation + 8-step local scan) ----------------
// grid (32 n-tiles, 256 m-tiles), 256 thr, 2 CTA/SM, 3-stage cp.async
__global__ void __launch_bounds__(NTHREADS, 2)
gemm_kernel(const float* __restrict__ bfw, const float* __restrict__ bbw)
{
    extern __shared__ __half smem[];
    const int tid  = threadIdx.x;
    const int lane = tid & 31;
    const int wid  = tid >> 5;                 // 0..7
    const int gid  = lane >> 2;                // 0..7
    const int tig  = lane & 3;                 // 0..3
    const int warp_m = (wid >> 1) * 32;        // 0,32,64,96
    const int warp_n = (wid & 1) * 48;         // 0,48

    const int n0    = blockIdx.x * BN;         // within one dir (1536/96=16 tiles/dir)
    const int mtile = blockIdx.y;              // seq block: s in [8*mtile, 8*mtile+8)
    const int m0    = mtile * BM;

    const __half* Ag = g_Xh + (size_t)m0 * DIN;
    const __half* Bg = g_Wh + (size_t)n0 * DIN;

    const uint32_t sbase = smem_u32(smem);
    // per stage: A at +0 (128*128B=16KB), B at +16KB (96*128B=12KB)

    auto load_stage = [&](int kt) {
        const int k0 = kt * BK;
        const uint32_t sb = sbase + (kt % NSTAGE) * STAGE_BYTES;
        #pragma unroll
        for (int i = 0; i < 4; i++) {                          // A: 1024 chunks
            int idx = tid + i * NTHREADS;
            int row = idx >> 3, c16 = idx & 7;
            uint32_t off = row * 128 + ((c16 ^ (row & 7)) << 4);
            cp_async16(sb + off, Ag + (size_t)row * DIN + k0 + c16 * 8);
        }
        #pragma unroll
        for (int i = 0; i < 3; i++) {                          // B: 768 chunks
            int idx = tid + i * NTHREADS;
            int row = idx >> 3, c16 = idx & 7;
            uint32_t off = BM * 128 + row * 128 + ((c16 ^ (row & 7)) << 4);
            cp_async16(sb + off, Bg + (size_t)row * DIN + k0 + c16 * 8);
        }
        cp_commit();
    };

    float acc[2][6][4];
    #pragma unroll
    for (int mi = 0; mi < 2; mi++)
        #pragma unroll
        for (int ni = 0; ni < 6; ni++)
            #pragma unroll
            for (int k = 0; k < 4; k++) acc[mi][ni][k] = 0.0f;

    const int lrow = lane & 15;
    const int lhi  = lane >> 4;
    uint32_t a_base[2], a_key[2];
    #pragma unroll
    for (int mi = 0; mi < 2; mi++) {
        int r = warp_m + mi * 16 + lrow;
        a_base[mi] = (uint32_t)r * 128;
        a_key[mi]  = r & 7;
    }
    uint32_t b_base[3], b_key[3];
    #pragma unroll
    for (int nj = 0; nj < 3; nj++) {
        int r = warp_n + nj * 16 + lrow;
        b_base[nj] = BM * 128 + (uint32_t)r * 128;
        b_key[nj]  = r & 7;
    }

    load_stage(0);
    load_stage(1);

    for (int kt = 0; kt < KTILES; kt++) {
        if (kt + 2 < KTILES)       { load_stage(kt + 2); cp_wait<2>(); }
        else if (kt + 2 == KTILES) { cp_wait<1>(); }
        else                       { cp_wait<0>(); }
        __syncthreads();

        const uint32_t sb = sbase + (kt % NSTAGE) * STAGE_BYTES;

        #pragma unroll
        for (int ks = 0; ks < 4; ks++) {
            const uint32_t c16 = (uint32_t)(ks * 2 + lhi);
            uint32_t a[2][4];
            #pragma unroll
            for (int mi = 0; mi < 2; mi++)
                ldsm_x4(a[mi], sb + a_base[mi] + ((c16 ^ a_key[mi]) << 4));
            uint32_t b[3][4];
            #pragma unroll
            for (int nj = 0; nj < 3; nj++)
                ldsm_x4(b[nj], sb + b_base[nj] + ((c16 ^ b_key[nj]) << 4));
            #pragma unroll
            for (int mi = 0; mi < 2; mi++)
                #pragma unroll
                for (int nj = 0; nj < 3; nj++) {
                    mma_f16(acc[mi][2 * nj],     a[mi], b[nj][0], b[nj][2]);
                    mma_f16(acc[mi][2 * nj + 1], a[mi], b[nj][1], b[nj][3]);
                }
        }
        __syncthreads();
    }

    // ---- stage accs through smem ----
    float* sred = (float*)smem;                  // 128 x 100 pitch = 51.2KB
    #pragma unroll
    for (int mi = 0; mi < 2; mi++) {
        int r0 = warp_m + mi * 16 + gid;
        #pragma unroll
        for (int ni = 0; ni < 6; ni++) {
            int cl = warp_n + ni * 8 + tig * 2;
            *(float2*)(sred + r0 * EPIPITCH + cl) =
                make_float2(acc[mi][ni][0], acc[mi][ni][1]);
            *(float2*)(sred + (r0 + 8) * EPIPITCH + cl) =
                make_float2(acc[mi][ni][2], acc[mi][ni][3]);
        }
    }
    __syncthreads();

    // ---- fused activation + 8-step local scan ----
    // thread t: h_local = t&31, batch = (t>>5) then +8. 8 seq steps in scan order.
    const int hl   = tid & 31;
    const int bgr  = tid >> 5;                   // 0..7
    const int dir  = n0 / NDIR;
    const int hg   = (n0 % NDIR) / 3 + hl;
    const float* bias = dir ? bbw : bfw;
    const float bz = bias[hg];
    const float bf = bias[HID + hg];
    const float bo = bias[2 * HID + hg];
    const int chunk = dir ? (NCHUNK - 1 - mtile) : mtile;   // scan-order chunk id

    #pragma unroll
    for (int pass = 0; pass < 2; pass++) {
        const int b = bgr + pass * 8;
        float P = 1.0f, H = 0.0f;
        #pragma unroll
        for (int ii = 0; ii < 8; ii++) {
            const int s_local = dir ? (7 - ii) : ii;         // scan order
            const float* rp = sred + (s_local * 16 + b) * EPIPITCH + hl * 3;
            float z = fast_tanh(rp[0] + bz);
            float f = fast_sig(rp[1] + bf);
            float o = fast_sig(rp[2] + bo);
            float a = 1.0f - f;
            H = fmaf(a, H, f * z);
            P *= a;
            const int s = mtile * 8 + s_local;
            size_t idx = ((size_t)(s * BATCH + b) * 2 + dir) * HID + hg;
            g_ph[idx] = __floats2half2_rn(P, H);
            g_o[idx]  = __float2half_rn(o);
        }
        const int ch = dir * 8192 + b * 512 + hg;
        g_AC[(size_t)ch * NCHUNK + chunk] = make_float2(P, H);
    }
}

// ---------------- combine: chunk aggregates -> superchunk carry-ins ----------------
// 1024 blocks x 256 thr; block covers 16 channels x 16 superchunks.
__global__ void __launch_bounds__(256)
combine_kernel()
{
    __shared__ float2 sAC[16][17];
    const int tid = threadIdx.x;
    const int cl  = tid >> 4;                    // channel-local 0..15
    const int sc  = tid & 15;                    // superchunk 0..15
    const int ch  = blockIdx.x * 16 + cl;

    // reduce 16 chunk aggregates (scan order) into one superchunk aggregate
    const float4* p = (const float4*)(g_AC + (size_t)ch * NCHUNK + sc * 16);
    float SA = 1.0f, SC = 0.0f;
    #pragma unroll
    for (int q = 0; q < 8; q++) {
        float4 v = p[q];                         // (A0,C0,A1,C1)
        SC = fmaf(v.x, SC, v.y); SA *= v.x;
        SC = fmaf(v.z, SC, v.w); SA *= v.z;
    }
    sAC[cl][sc] = make_float2(SA, SC);
    __syncthreads();

    if (tid < 16) {                              // serial 16-scan per channel
        const int c = tid;
        const int chh = blockIdx.x * 16 + c;
        float h = 0.0f;
        #pragma unroll
        for (int s = 0; s < NSUPER; s++) {
            g_hsup[(size_t)chh * NSUPER + s] = h;
            float2 v = sAC[c][s];
            h = fmaf(v.x, h, v.y);
        }
    }
}

// ---------------- final: apply carries, write output ----------------
// grid 2048 x 128: block = (channel-group of 128) x superchunk; 128 positions/thread
__global__ void __launch_bounds__(128)
final_kernel(float* __restrict__ out)
{
    const int sc  = blockIdx.x & 15;
    const int ch  = (blockIdx.x >> 4) * 128 + threadIdx.x;
    const int dir = ch >> 13;
    const int b   = (ch >> 9) & 15;
    const int hg  = ch & 511;

    float h = g_hsup[(size_t)ch * NSUPER + sc];

    const int p0 = sc * 128;                     // first scan-order position
    #pragma unroll 2
    for (int kl = 0; kl < 16; kl++) {
        float hs = h;
        #pragma unroll
        for (int i = 0; i < 8; i++) {
            const int p = p0 + kl * 8 + i;
            const int s = dir ? (SEQ - 1 - p) : p;
            const size_t idx = ((size_t)(s * BATCH + b) * 2 + dir) * HID + hg;
            float2 ph = __half22float2(g_ph[idx]);
            float o   = __half2float(g_o[idx]);
            hs = fmaf(ph.x, h, ph.y);            // h_s = H_s + P_s * h_carry
            out[(size_t)s * (BATCH * 2 * HID) + b * (2 * HID) + dir * HID + hg] = o * hs;
        }
        h = hs;                                  // carry = last position's h
    }
}

// ---------------- launch ----------------
extern "C" void kernel_launch(void* const* d_in, const int* in_sizes, int n_in,
                              void* d_out, int out_size)
{
    (void)in_sizes; (void)n_in; (void)out_size;
    const float* X   = (const float*)d_in[0];
    const float* Wfw = (const float*)d_in[1];
    const float* bfw = (const float*)d_in[2];
    const float* Wbw = (const float*)d_in[3];
    const float* bbw = (const float*)d_in[4];
    float* out = (float*)d_out;

    cudaFuncSetAttribute(gemm_kernel,
                         cudaFuncAttributeMaxDynamicSharedMemorySize, SMEM_BYTES);

    convert_kernel<<<17920, 256>>>(X, Wfw, Wbw);
    gemm_kernel<<<dim3(32, 256), NTHREADS, SMEM_BYTES>>>(bfw, bbw);
    combine_kernel<<<NCH / 16, 256>>>();
    final_kernel<<<(NCH / 128) * NSUPER, 128>>>(out);
}